// round 13
// baseline (speedup 1.0000x reference)
#include <cuda_runtime.h>
#include <cuda_bf16.h>
#include <cstdint>

// Problem constants: outputs [64,512,1000] f32, labels [64,512] i32
#define LBL 1000

__device__ __align__(16) int g_first[1024];     // static zero-init; k_scan re-zeros
__device__ __align__(16) int g_argm_ev[1024];   // argmax of each label's first row
__device__ __align__(16) int g_idx[1024];       // pinv (inverse permutation)

static __device__ __forceinline__ uint32_t smem_u32(const void* p) {
    uint32_t a;
    asm("{ .reg .u64 t; cvta.to.shared.u64 t, %1; cvt.u32.u64 %0, t; }"
        : "=r"(a) : "l"(p));
    return a;
}

// ---------------------------------------------------------------------------
// K0: first occurrence per label, from labels only.
// Encoded as max(N - i) so the empty state is 0 (static zero init, no reset
// kernel; k_scan re-zeros after consuming). 32768 atomics over 1000 addrs.
// ---------------------------------------------------------------------------
__global__ __launch_bounds__(256) void k_first(const int* __restrict__ labels,
                                               int N) {
    int i = blockIdx.x * blockDim.x + threadIdx.x;
    if (i < N) atomicMax(&g_first[labels[i]], N - i);
}

// ---------------------------------------------------------------------------
// K1: argmax of ONLY the first-occurrence rows (<=1000 rows, ~4 MB).
// One warp per label. PDL: dispatched under k_first, syncs at top.
// ---------------------------------------------------------------------------
__global__ __launch_bounds__(256) void k_argmax_ev(const float* __restrict__ in,
                                                   int N) {
    cudaGridDependencySynchronize();             // wait k_first (PDL)

    int t    = (blockIdx.x * blockDim.x + threadIdx.x) >> 5;   // label id
    int lane = threadIdx.x & 31;
    if (t >= LBL) return;
    int enc = g_first[t];
    if (enc <= 0) return;            // label never occurs
    int row = N - enc;               // first-occurrence row

    const float4* rp = reinterpret_cast<const float4*>(in) + (size_t)row * 250;
    float bv = -3.402823466e38f;
    int   bi = 0;
#pragma unroll
    for (int it = 0; it < 7; ++it) {             // k = lane + 32*it <= 223
        int k = lane + it * 32;
        float4 v = rp[k];
        int b = k * 4;
        if (v.x > bv) { bv = v.x; bi = b;     }
        if (v.y > bv) { bv = v.y; bi = b + 1; }
        if (v.z > bv) { bv = v.z; bi = b + 2; }
        if (v.w > bv) { bv = v.w; bi = b + 3; }
    }
    if (lane < 26) {                              // tail: k = lane + 224 < 250
        int k = lane + 224;
        float4 v = rp[k];
        int b = k * 4;
        if (v.x > bv) { bv = v.x; bi = b;     }
        if (v.y > bv) { bv = v.y; bi = b + 1; }
        if (v.z > bv) { bv = v.z; bi = b + 2; }
        if (v.w > bv) { bv = v.w; bi = b + 3; }
    }
#pragma unroll
    for (int off = 16; off > 0; off >>= 1) {
        float ov = __shfl_down_sync(0xFFFFFFFFu, bv, off);
        int   oi = __shfl_down_sync(0xFFFFFFFFu, bi, off);
        if (ov > bv || (ov == bv && oi < bi)) { bv = ov; bi = oi; }
    }
    if (lane == 0) g_argm_ev[t] = bi;
}

// ---------------------------------------------------------------------------
// K2: single block. PDL: smem init runs under k_argmax_ev, sync before
// reading g_first / g_argm_ev.
//   Phase A: rank events by row via 32768-bit bitmap + popc prefix-sum.
//   Phase B: warp-speculative batch scan (warp 0).
//   Output: g_idx = pinv directly (gather scatters with pinv).
// ---------------------------------------------------------------------------
__global__ __launch_bounds__(1024) void k_scan(int N) {
    __shared__ unsigned  sbit[1024];   // 32768-bit row bitmap
    __shared__ int       sexc[1024];   // exclusive popc prefix per word
    __shared__ long long ev[1088];     // packed (m << 32) | lab, sorted by row
    __shared__ int       pinv[1024];
    __shared__ int       stamp[1024];  // per-cell lane stamps for hazard detect
    __shared__ int       wsum[32];
    __shared__ int       sE;

    int t = threadIdx.x;
    int lane = t & 31, w = t >> 5;

    // ---- prework (independent of predecessors) ----------------------------
    sbit[t]  = 0u;
    pinv[t]  = t;
    stamp[t] = 63;
    ev[t]    = ((long long)1023 << 32) | 1023u;     // dummy everywhere
    if (t < 64) ev[1024 + t] = ((long long)1023 << 32) | 1023u;

    cudaGridDependencySynchronize();   // wait k_argmax_ev (PDL, transitive)

    int enc = (t < LBL) ? g_first[t] : 0;
    g_first[t] = 0;                    // reset for next graph replay
    int myf = (enc > 0) ? (N - enc) : -1;
    __syncthreads();

    if (myf >= 0)
        atomicOr(&sbit[myf >> 5], 1u << (myf & 31));
    __syncthreads();

    // block prefix-sum of per-word popcounts
    unsigned word = sbit[t];
    int c = __popc(word);
    int x = c;
#pragma unroll
    for (int o = 1; o < 32; o <<= 1) {
        int y = __shfl_up_sync(0xFFFFFFFFu, x, o);
        if (lane >= o) x += y;
    }
    if (lane == 31) wsum[w] = x;
    __syncthreads();
    if (t < 32) {
        int v = wsum[t];
        int iv = v;
#pragma unroll
        for (int o = 1; o < 32; o <<= 1) {
            int y = __shfl_up_sync(0xFFFFFFFFu, iv, o);
            if (t >= o) iv += y;
        }
        wsum[t] = iv - v;          // exclusive warp offset
        if (t == 31) sE = iv;      // total number of events
    }
    __syncthreads();
    sexc[t] = wsum[w] + (x - c);
    __syncthreads();

    if (myf >= 0) {
        unsigned wv = sbit[myf >> 5];
        int rank = sexc[myf >> 5] + __popc(wv & ((1u << (myf & 31)) - 1u));
        ev[rank] = ((long long)g_argm_ev[t] << 32) | (unsigned)t;
    }
    __syncthreads();

    // Phase B: warp-speculative batch loop (warp 0 only)
    if (t < 32) {
        const unsigned FULL = 0xFFFFFFFFu;
        int E = sE;
        int base = 0;
        while (base < E) {
            long long ee = ev[base + lane];
            int m   = (int)(ee >> 32);
            int lab = (int)(ee & 0xFFFFFFFFLL);
            int r   = pinv[m];                // speculative (round-start state)
            int pl  = pinv[lab];
            int pr  = pinv[r];
            atomicMin(&stamp[r],   lane);
            atomicMin(&stamp[lab], lane);
            __syncwarp(FULL);
            int hz = (stamp[m] < lane) | (stamp[r] < lane) | (stamp[lab] < lane);
            unsigned bal = __ballot_sync(FULL, hz);
            int f = bal ? (__ffs(bal) - 1) : 32;    // f >= 1 always (lane 0 safe)
            stamp[r]   = 63;                   // reset stamps (post-ballot sync)
            stamp[lab] = 63;
            if (lane < f) {                    // commit conflict-free prefix
                pinv[r]   = pl;
                pinv[lab] = pr;
            }
            __syncwarp(FULL);
            base += f;
        }
    }
    __syncthreads();

    if (t < LBL) g_idx[t] = pinv[t];   // store pinv directly (scatter gather)
}

// ---------------------------------------------------------------------------
// K3: out[n, pinv[k]] = in[n, k]. Double-pumped register buffer (v[4], two
// batches) to cut regs to ~40 => 6 blocks/SM (75% occ). Batch 0 LDGs issue
// BEFORE the PDL sync (overlap k_scan); batch 1 loads after batch-0 scatter.
// Permuted scalar-STS scatter + single TMA bulk store per row.
// ---------------------------------------------------------------------------
__global__ __launch_bounds__(256, 6) void k_gather(const float* __restrict__ in,
                                                   float* __restrict__ out, int N) {
    __shared__ int4 sidx[250];                       // pinv, packed
    __shared__ __align__(16) float srow[8][1000];    // 4 KB slab per warp

    int t    = threadIdx.x;
    int wid  = t >> 5;
    int lane = t & 31;

    int row = blockIdx.x * 8 + wid;
    const float4* rp = reinterpret_cast<const float4*>(in + (size_t)row * 1000);

    // ---- prework: batch 0 loads (k = lane .. lane+96; overlaps k_scan) ----
    float4 v[4];
    if (row < N) {
#pragma unroll
        for (int it = 0; it < 4; ++it)
            v[it] = __ldcs(&rp[lane + it * 32]);
    }

    cudaGridDependencySynchronize();   // wait k_scan (PDL) -> g_idx ready

    if (t < 250) sidx[t] = reinterpret_cast<const int4*>(g_idx)[t];
    __syncthreads();

    if (row < N) {
        float* my = &srow[wid][0];
        // scatter batch 0
#pragma unroll
        for (int it = 0; it < 4; ++it) {
            int4 p = sidx[lane + it * 32];
            my[p.x] = v[it].x;
            my[p.y] = v[it].y;
            my[p.z] = v[it].z;
            my[p.w] = v[it].w;
        }
        // batch 1 loads (reuse v regs)
#pragma unroll
        for (int it = 0; it < 4; ++it) {
            int k = lane + (it + 4) * 32;
            if (k < 250) v[it] = __ldcs(&rp[k]);
        }
        // scatter batch 1
#pragma unroll
        for (int it = 0; it < 4; ++it) {
            int k = lane + (it + 4) * 32;
            if (k < 250) {
                int4 p = sidx[k];
                my[p.x] = v[it].x;
                my[p.y] = v[it].y;
                my[p.z] = v[it].z;
                my[p.w] = v[it].w;
            }
        }
        // order the generic STS above before the async-proxy smem reads
        asm volatile("fence.proxy.async.shared::cta;" ::: "memory");
        __syncwarp();
        if (lane == 0) {
            uint32_t saddr = smem_u32(my);
            float*   gdst  = out + (size_t)row * 1000;
            asm volatile(
                "cp.async.bulk.global.shared::cta.bulk_group [%0], [%1], %2;"
                :: "l"(gdst), "r"(saddr), "r"(4000) : "memory");
            asm volatile("cp.async.bulk.commit_group;" ::: "memory");
            asm volatile("cp.async.bulk.wait_group 0;" ::: "memory");
        }
        __syncwarp();
    }
}

// ---------------------------------------------------------------------------
// host: PDL launches (programmatic stream serialization on the capture stream)
// ---------------------------------------------------------------------------
template <typename F, typename... Args>
static void launch_pdl(F func, dim3 grid, dim3 block, Args... args) {
    cudaLaunchConfig_t cfg = {};
    cfg.gridDim  = grid;
    cfg.blockDim = block;
    cfg.dynamicSmemBytes = 0;
    cfg.stream = 0;                      // legacy default stream (captured)
    cudaLaunchAttribute attr[1];
    attr[0].id = cudaLaunchAttributeProgrammaticStreamSerialization;
    attr[0].val.programmaticStreamSerializationAllowed = 1;
    cfg.attrs = attr;
    cfg.numAttrs = 1;
    cudaLaunchKernelEx(&cfg, func, args...);
}

extern "C" void kernel_launch(void* const* d_in, const int* in_sizes, int n_in,
                              void* d_out, int out_size) {
    const float* in     = (const float*)d_in[0];
    const int*   labels = (const int*)d_in[1];
    float*       out    = (float*)d_out;
    int N = in_sizes[1];   // 32768 rows; L = 1000

    k_first<<<(N + 255) / 256, 256>>>(labels, N);
    launch_pdl(k_argmax_ev, dim3((LBL * 32 + 255) / 256), dim3(256), in, N);
    launch_pdl(k_scan,      dim3(1),                      dim3(1024), N);
    launch_pdl(k_gather,    dim3((N + 7) / 8),            dim3(256), in, out, N);
}

// round 14
// speedup vs baseline: 1.1028x; 1.1028x over previous
#include <cuda_runtime.h>
#include <cuda_bf16.h>
#include <cstdint>

// Problem constants: outputs [64,512,1000] f32, labels [64,512] i32
#define LBL 1000

__device__ __align__(16) int g_first[1024];     // static zero-init; k_scan re-zeros
__device__ __align__(16) int g_argm_ev[1024];   // argmax of each label's first row
__device__ __align__(16) int g_idx[1024];       // pinv (inverse permutation)
__device__ unsigned g_done;                     // monotonic: ++ per replay by k_scan
__device__ unsigned g_target;                   // snapshot: g_done+1 (by k_first)

static __device__ __forceinline__ uint32_t smem_u32(const void* p) {
    uint32_t a;
    asm("{ .reg .u64 t; cvta.to.shared.u64 t, %1; cvt.u32.u64 %0, t; }"
        : "=r"(a) : "l"(p));
    return a;
}

// ---------------------------------------------------------------------------
// K0: first occurrence per label, from labels only.
// Encoded as max(N - i) so the empty state is 0 (static zero init, no reset
// kernel; k_scan re-zeros after consuming). Also snapshots the gather-release
// target (replays are stream-serialized, so g_done is quiescent here).
// ---------------------------------------------------------------------------
__global__ __launch_bounds__(256) void k_first(const int* __restrict__ labels,
                                               int N) {
    if (blockIdx.x == 0 && threadIdx.x == 0)
        g_target = g_done + 1;
    int i = blockIdx.x * blockDim.x + threadIdx.x;
    if (i < N) atomicMax(&g_first[labels[i]], N - i);
}

// ---------------------------------------------------------------------------
// K1: argmax of ONLY the first-occurrence rows (<=1000 rows, ~4 MB).
// One warp per label. PDL: dispatched under k_first, syncs at top.
// ---------------------------------------------------------------------------
__global__ __launch_bounds__(256) void k_argmax_ev(const float* __restrict__ in,
                                                   int N) {
    cudaGridDependencySynchronize();             // wait k_first (PDL)

    int t    = (blockIdx.x * blockDim.x + threadIdx.x) >> 5;   // label id
    int lane = threadIdx.x & 31;
    if (t >= LBL) return;
    int enc = g_first[t];
    if (enc <= 0) return;            // label never occurs
    int row = N - enc;               // first-occurrence row

    const float4* rp = reinterpret_cast<const float4*>(in) + (size_t)row * 250;
    float bv = -3.402823466e38f;
    int   bi = 0;
#pragma unroll
    for (int it = 0; it < 7; ++it) {             // k = lane + 32*it <= 223
        int k = lane + it * 32;
        float4 v = rp[k];
        int b = k * 4;
        if (v.x > bv) { bv = v.x; bi = b;     }
        if (v.y > bv) { bv = v.y; bi = b + 1; }
        if (v.z > bv) { bv = v.z; bi = b + 2; }
        if (v.w > bv) { bv = v.w; bi = b + 3; }
    }
    if (lane < 26) {                              // tail: k = lane + 224 < 250
        int k = lane + 224;
        float4 v = rp[k];
        int b = k * 4;
        if (v.x > bv) { bv = v.x; bi = b;     }
        if (v.y > bv) { bv = v.y; bi = b + 1; }
        if (v.z > bv) { bv = v.z; bi = b + 2; }
        if (v.w > bv) { bv = v.w; bi = b + 3; }
    }
#pragma unroll
    for (int off = 16; off > 0; off >>= 1) {
        float ov = __shfl_down_sync(0xFFFFFFFFu, bv, off);
        int   oi = __shfl_down_sync(0xFFFFFFFFu, bi, off);
        if (ov > bv || (ov == bv && oi < bi)) { bv = ov; bi = oi; }
    }
    if (lane == 0) g_argm_ev[t] = bi;
}

// ---------------------------------------------------------------------------
// K2: single block. Triggers programmatic launch of k_gather AT ENTRY so the
// gather's wave-1 row loads overlap this kernel. Releases the gather via
// g_done++ (after threadfence) when g_idx is published.
//   Phase A: rank events by row via 32768-bit bitmap + popc prefix-sum.
//   Phase B: warp-speculative batch scan (warp 0).
// ---------------------------------------------------------------------------
__global__ __launch_bounds__(1024) void k_scan(int N) {
    cudaTriggerProgrammaticLaunchCompletion();   // let k_gather launch NOW

    __shared__ unsigned  sbit[1024];   // 32768-bit row bitmap
    __shared__ int       sexc[1024];   // exclusive popc prefix per word
    __shared__ long long ev[1088];     // packed (m << 32) | lab, sorted by row
    __shared__ int       pinv[1024];
    __shared__ int       stamp[1024];  // per-cell lane stamps for hazard detect
    __shared__ int       wsum[32];
    __shared__ int       sE;

    int t = threadIdx.x;
    int lane = t & 31, w = t >> 5;

    // ---- prework (independent of predecessors) ----------------------------
    sbit[t]  = 0u;
    pinv[t]  = t;
    stamp[t] = 63;
    ev[t]    = ((long long)1023 << 32) | 1023u;     // dummy everywhere
    if (t < 64) ev[1024 + t] = ((long long)1023 << 32) | 1023u;

    cudaGridDependencySynchronize();   // wait k_argmax_ev (PDL)

    int enc = (t < LBL) ? g_first[t] : 0;
    g_first[t] = 0;                    // reset for next graph replay
    int myf = (enc > 0) ? (N - enc) : -1;
    __syncthreads();

    if (myf >= 0)
        atomicOr(&sbit[myf >> 5], 1u << (myf & 31));
    __syncthreads();

    // block prefix-sum of per-word popcounts
    unsigned word = sbit[t];
    int c = __popc(word);
    int x = c;
#pragma unroll
    for (int o = 1; o < 32; o <<= 1) {
        int y = __shfl_up_sync(0xFFFFFFFFu, x, o);
        if (lane >= o) x += y;
    }
    if (lane == 31) wsum[w] = x;
    __syncthreads();
    if (t < 32) {
        int v = wsum[t];
        int iv = v;
#pragma unroll
        for (int o = 1; o < 32; o <<= 1) {
            int y = __shfl_up_sync(0xFFFFFFFFu, iv, o);
            if (t >= o) iv += y;
        }
        wsum[t] = iv - v;          // exclusive warp offset
        if (t == 31) sE = iv;      // total number of events
    }
    __syncthreads();
    sexc[t] = wsum[w] + (x - c);
    __syncthreads();

    if (myf >= 0) {
        unsigned wv = sbit[myf >> 5];
        int rank = sexc[myf >> 5] + __popc(wv & ((1u << (myf & 31)) - 1u));
        ev[rank] = ((long long)g_argm_ev[t] << 32) | (unsigned)t;
    }
    __syncthreads();

    // Phase B: warp-speculative batch loop (warp 0 only)
    if (t < 32) {
        const unsigned FULL = 0xFFFFFFFFu;
        int E = sE;
        int base = 0;
        while (base < E) {
            long long ee = ev[base + lane];
            int m   = (int)(ee >> 32);
            int lab = (int)(ee & 0xFFFFFFFFLL);
            atomicMin(&stamp[lab], lane);     // no dependence on r: issue early
            int r   = pinv[m];                // speculative (round-start state)
            int pl  = pinv[lab];
            int pr  = pinv[r];
            atomicMin(&stamp[r], lane);
            __syncwarp(FULL);
            int hz = (stamp[m] < lane) | (stamp[r] < lane) | (stamp[lab] < lane);
            unsigned bal = __ballot_sync(FULL, hz);
            int f = bal ? (__ffs(bal) - 1) : 32;    // f >= 1 always (lane 0 safe)
            stamp[r]   = 63;                   // reset stamps (post-ballot sync)
            stamp[lab] = 63;
            if (lane < f) {                    // commit conflict-free prefix
                pinv[r]   = pl;
                pinv[lab] = pr;
            }
            __syncwarp(FULL);
            base += f;
        }
    }
    __syncthreads();

    if (t < LBL) g_idx[t] = pinv[t];   // publish pinv
    __threadfence();
    __syncthreads();
    if (t == 0) atomicAdd(&g_done, 1u);        // release the gather
}

// ---------------------------------------------------------------------------
// K3: out[n, pinv[k]] = in[n, k]. Launched programmatically while k_scan runs:
// issues ALL row loads (MLP=8, wave-1 ~24 MB overlaps the scan), then spins on
// g_done. sidx read via __ldcg (L2-coherent). Scatter-STS + TMA bulk store.
// ---------------------------------------------------------------------------
__global__ __launch_bounds__(256) void k_gather(const float* __restrict__ in,
                                                float* __restrict__ out, int N) {
    __shared__ int4 sidx[250];                       // pinv, packed
    __shared__ __align__(16) float srow[8][1000];    // 4 KB slab per warp

    int t    = threadIdx.x;
    int wid  = t >> 5;
    int lane = t & 31;

    // ---- prework: all row loads in flight (overlaps k_scan) ---------------
    int row = blockIdx.x * 8 + wid;
    float4 v[8];
    if (row < N) {
        const float4* rp = reinterpret_cast<const float4*>(in + (size_t)row * 1000);
#pragma unroll
        for (int it = 0; it < 8; ++it) {
            int k = lane + it * 32;
            if (k < 250) v[it] = __ldcs(&rp[k]);
        }
    }

    // ---- wait for g_idx (monotonic flag; target snapshotted by k_first) ---
    if (t == 0) {
        unsigned tgt = __ldcg(&g_target);
        while (__ldcg(&g_done) < tgt) __nanosleep(64);
    }
    __syncthreads();

    if (t < 250) sidx[t] = __ldcg(reinterpret_cast<const int4*>(g_idx) + t);
    __syncthreads();

    if (row < N) {
        float* my = &srow[wid][0];
#pragma unroll
        for (int it = 0; it < 8; ++it) {
            int k = lane + it * 32;
            if (k < 250) {
                int4 p = sidx[k];
                my[p.x] = v[it].x;     // permuted scatter into smem
                my[p.y] = v[it].y;
                my[p.z] = v[it].z;
                my[p.w] = v[it].w;
            }
        }
        // order the generic STS above before the async-proxy smem reads
        asm volatile("fence.proxy.async.shared::cta;" ::: "memory");
        __syncwarp();
        if (lane == 0) {
            uint32_t saddr = smem_u32(my);
            float*   gdst  = out + (size_t)row * 1000;
            asm volatile(
                "cp.async.bulk.global.shared::cta.bulk_group [%0], [%1], %2;"
                :: "l"(gdst), "r"(saddr), "r"(4000) : "memory");
            asm volatile("cp.async.bulk.commit_group;" ::: "memory");
            asm volatile("cp.async.bulk.wait_group 0;" ::: "memory");
        }
        __syncwarp();
    }
}

// ---------------------------------------------------------------------------
// host: PDL launches (programmatic stream serialization on the capture stream)
// ---------------------------------------------------------------------------
template <typename F, typename... Args>
static void launch_pdl(F func, dim3 grid, dim3 block, Args... args) {
    cudaLaunchConfig_t cfg = {};
    cfg.gridDim  = grid;
    cfg.blockDim = block;
    cfg.dynamicSmemBytes = 0;
    cfg.stream = 0;                      // legacy default stream (captured)
    cudaLaunchAttribute attr[1];
    attr[0].id = cudaLaunchAttributeProgrammaticStreamSerialization;
    attr[0].val.programmaticStreamSerializationAllowed = 1;
    cfg.attrs = attr;
    cfg.numAttrs = 1;
    cudaLaunchKernelEx(&cfg, func, args...);
}

extern "C" void kernel_launch(void* const* d_in, const int* in_sizes, int n_in,
                              void* d_out, int out_size) {
    const float* in     = (const float*)d_in[0];
    const int*   labels = (const int*)d_in[1];
    float*       out    = (float*)d_out;
    int N = in_sizes[1];   // 32768 rows; L = 1000

    k_first<<<(N + 255) / 256, 256>>>(labels, N);
    launch_pdl(k_argmax_ev, dim3((LBL * 32 + 255) / 256), dim3(256), in, N);
    launch_pdl(k_scan,      dim3(1),                      dim3(1024), N);
    launch_pdl(k_gather,    dim3((N + 7) / 8),            dim3(256), in, out, N);
}